// round 3
// baseline (speedup 1.0000x reference)
#include <cuda_runtime.h>

// Problem constants
#define BB   4
#define TT   32
#define NN   1000
#define CC   64
#define EE   16000
#define BT   (BB*TT)           // 128
#define BTN  (BT*NN)           // 128000
#define ELEM (BTN*CC)          // 8192000
#define EPSV 1e-5f

// ---------------- device scratch (allocation-free: __device__ globals) ------
__device__ __align__(16) float g_xw[ELEM];   // x @ W
__device__ __align__(16) float g_so[ELEM];   // GCN aggregate (pre-BN1)
__device__ __align__(16) float g_y2[ELEM];   // conv output (pre-BN2)
__device__ float g_wt[9 * CC * CC];          // conv weights transposed: [k][ci][c]
__device__ int   g_cnt[NN];
__device__ int   g_cur[NN];
__device__ int   g_off[NN + 1];
__device__ float g_dinv[NN];
__device__ int   g_src[EE];
__device__ float g_nrm[EE];
__device__ float g_stats[4 * CC];            // sum1, sq1, sum2, sq2
__device__ float g_s1[CC], g_t1[CC], g_s2[CC], g_t2[CC];

// ---------------- init -------------------------------------------------------
__global__ void k_init() {
    int i = blockIdx.x * blockDim.x + threadIdx.x;
    if (i < NN) { g_cnt[i] = 0; g_cur[i] = 0; }
    if (i < 4 * CC) g_stats[i] = 0.f;
}

// ---------------- degree histogram (edge_index is int32: JAX x64 disabled) --
__global__ void k_deg(const int* __restrict__ ei) {
    int e = blockIdx.x * blockDim.x + threadIdx.x;
    if (e < EE) atomicAdd(&g_cnt[ei[EE + e]], 1);
}

// ---------------- scan: CSR offsets + dinv (single block) -------------------
__global__ void k_scan() {
    __shared__ int s[1024];
    int tid = threadIdx.x;
    int v = (tid < NN) ? g_cnt[tid] : 0;
    s[tid] = v;
    for (int d = 1; d < 1024; d <<= 1) {
        __syncthreads();
        int t = (tid >= d) ? s[tid - d] : 0;
        __syncthreads();
        s[tid] += t;
    }
    __syncthreads();
    if (tid < NN) {
        g_off[tid] = s[tid] - v;                    // exclusive scan
        g_dinv[tid] = rsqrtf((float)(v + 1));       // +1 self loop
    }
    if (tid == NN - 1) g_off[NN] = s[tid];
}

// ---------------- CSR fill ---------------------------------------------------
__global__ void k_fill(const int* __restrict__ ei) {
    int e = blockIdx.x * blockDim.x + threadIdx.x;
    if (e < EE) {
        int sr = ei[e], ds = ei[EE + e];
        int pos = atomicAdd(&g_cur[ds], 1);
        int idx = g_off[ds] + pos;
        g_src[idx] = sr;
        g_nrm[idx] = g_dinv[sr] * g_dinv[ds];
    }
}

// ---------------- conv weight transpose: g_wt[(k*64+ci)*64+c] ---------------
__global__ void k_wt(const float* __restrict__ cw) {
    int i = blockIdx.x * blockDim.x + threadIdx.x;  // over 64*64*9
    if (i < CC * CC * 9) {
        int c  = i / (CC * 9);
        int ci = (i / 9) % CC;
        int k  = i % 9;
        g_wt[(k * CC + ci) * CC + c] = cw[i];
    }
}

// ---------------- xw = x @ W  (tile 64x64, 64 threads, 8x8 microtile) -------
__global__ void __launch_bounds__(64) k_xw(const float* __restrict__ x,
                                           const float* __restrict__ W) {
    __shared__ float Xs[CC * 65];   // transposed: Xs[ci][row], pad 65
    __shared__ float Ws[CC * CC];   // Ws[ci][c]
    int tid = threadIdx.x;
    int r0 = blockIdx.x * 64;       // 2000 blocks * 64 rows = 128000
    int ci = tid & 63;

    for (int i = tid; i < CC * CC; i += 64) Ws[i] = W[i];
    for (int i = tid; i < 64 * CC; i += 64) {
        int row = i >> 6;
        Xs[ci * 65 + row] = x[(r0 + row) * CC + ci];
    }
    __syncthreads();

    int tr = tid >> 3, tc = tid & 7;
    float acc[8][8];
#pragma unroll
    for (int i = 0; i < 8; i++)
#pragma unroll
        for (int j = 0; j < 8; j++) acc[i][j] = 0.f;

#pragma unroll 4
    for (int kk = 0; kk < CC; kk++) {
        float a[8], bw[8];
#pragma unroll
        for (int i = 0; i < 8; i++) a[i] = Xs[kk * 65 + tr * 8 + i];
#pragma unroll
        for (int j = 0; j < 8; j++) bw[j] = Ws[kk * CC + tc * 8 + j];
#pragma unroll
        for (int i = 0; i < 8; i++)
#pragma unroll
            for (int j = 0; j < 8; j++) acc[i][j] += a[i] * bw[j];
    }
#pragma unroll
    for (int i = 0; i < 8; i++) {
        int row = r0 + tr * 8 + i;
#pragma unroll
        for (int j = 0; j < 8; j++) g_xw[row * CC + tc * 8 + j] = acc[i][j];
    }
}

// ---------------- GCN aggregation: warp per (bt, n) -------------------------
__global__ void k_agg() {
    int warp = (blockIdx.x * blockDim.x + threadIdx.x) >> 5;
    int lane = threadIdx.x & 31;
    if (warp >= BTN) return;
    int bt = warp / NN;
    int n  = warp - bt * NN;
    int base_bt = bt * NN * CC;

    float dv = g_dinv[n];
    float self_w = dv * dv;
    float2 v = *(const float2*)&g_xw[base_bt + n * CC + lane * 2];
    float2 acc = make_float2(self_w * v.x, self_w * v.y);

    int e0 = g_off[n], e1 = g_off[n + 1];
    for (int e = e0; e < e1; e++) {
        int sr = g_src[e];
        float w = g_nrm[e];
        float2 u = *(const float2*)&g_xw[base_bt + sr * CC + lane * 2];
        acc.x += w * u.x;
        acc.y += w * u.y;
    }
    *(float2*)&g_so[warp * CC + lane * 2] = acc;
}

// ---------------- per-channel stats (sum, sumsq) ----------------------------
__global__ void k_stats(int sel) {
    const float* __restrict__ src = sel ? g_y2 : g_so;
    int base = sel * 2 * CC;
    int c = threadIdx.x & 63;
    int q = threadIdx.x >> 6;  // 0..3 (blockDim 256)
    float s = 0.f, s2 = 0.f;
    for (int r = blockIdx.x * 4 + q; r < BTN; r += gridDim.x * 4) {
        float v = src[r * CC + c];
        s += v;
        s2 += v * v;
    }
    __shared__ float sh[2][4][CC];
    sh[0][q][c] = s;
    sh[1][q][c] = s2;
    __syncthreads();
    if (q == 0) {
        s  = sh[0][0][c] + sh[0][1][c] + sh[0][2][c] + sh[0][3][c];
        s2 = sh[1][0][c] + sh[1][1][c] + sh[1][2][c] + sh[1][3][c];
        atomicAdd(&g_stats[base + c], s);
        atomicAdd(&g_stats[base + CC + c], s2);
    }
}

// ---------------- BN finalize: scale/shift per channel ----------------------
__global__ void k_fin(const float* __restrict__ gamma,
                      const float* __restrict__ beta, int sel) {
    int c = threadIdx.x;  // 64 threads
    int base = sel * 2 * CC;
    float inv_n = 1.f / (float)BTN;
    float mean = g_stats[base + c] * inv_n;
    float var  = g_stats[base + CC + c] * inv_n - mean * mean;
    float rstd = rsqrtf(var + EPSV);
    float s = gamma[c] * rstd;
    float t = beta[c] - mean * s;
    if (sel) { g_s2[c] = s; g_t2[c] = t; }
    else     { g_s1[c] = s; g_t1[c] = t; }
}

// ---------------- temporal conv (fused BN1+ReLU on load) --------------------
// out[bt, n, c] = sum_{k,ci} relu(bn1(so[b, t+k-4, n, ci])) * w[c, ci, k]
// tile: 64 n-rows x 64 c-cols per block, 64 threads, 8x8 microtile
__global__ void __launch_bounds__(64) k_conv() {
    __shared__ float As[CC * 65];   // transposed [ci][row]
    __shared__ float Ws[CC * CC];   // [ci][c]
    int tid = threadIdx.x;
    int nt = blockIdx.x & 15;       // 16 n-tiles
    int bt = blockIdx.x >> 4;       // 0..127
    int t = bt & 31;
    int n0 = nt * 64;
    int ci = tid & 63;
    float s1 = g_s1[ci], t1 = g_t1[ci];

    int tr = tid >> 3, tc = tid & 7;
    float acc[8][8];
#pragma unroll
    for (int i = 0; i < 8; i++)
#pragma unroll
        for (int j = 0; j < 8; j++) acc[i][j] = 0.f;

    for (int k = 0; k < 9; k++) {
        int tp = t + k - 4;
        if (tp < 0 || tp >= TT) continue;   // uniform per block
        int btp = (bt & ~31) + tp;          // b*32 + tp
        __syncthreads();
        for (int i = tid; i < CC * CC; i += 64) Ws[i] = g_wt[k * CC * CC + i];
        for (int i = tid; i < 64 * CC; i += 64) {
            int row = i >> 6;
            int n = n0 + row;
            float v = 0.f;
            if (n < NN) {
                v = g_so[(btp * NN + n) * CC + ci];
                v = fmaxf(v * s1 + t1, 0.f);
            }
            As[ci * 65 + row] = v;
        }
        __syncthreads();
#pragma unroll 4
        for (int kk = 0; kk < CC; kk++) {
            float a[8], bw[8];
#pragma unroll
            for (int i = 0; i < 8; i++) a[i] = As[kk * 65 + tr * 8 + i];
#pragma unroll
            for (int j = 0; j < 8; j++) bw[j] = Ws[kk * CC + tc * 8 + j];
#pragma unroll
            for (int i = 0; i < 8; i++)
#pragma unroll
                for (int j = 0; j < 8; j++) acc[i][j] += a[i] * bw[j];
        }
    }
#pragma unroll
    for (int i = 0; i < 8; i++) {
        int n = n0 + tr * 8 + i;
        if (n < NN) {
#pragma unroll
            for (int j = 0; j < 8; j++)
                g_y2[(bt * NN + n) * CC + tc * 8 + j] = acc[i][j];
        }
    }
}

// ---------------- final: relu(bn2(y2) + x) ----------------------------------
__global__ void k_final(const float* __restrict__ x, float* __restrict__ out) {
    int i = blockIdx.x * blockDim.x + threadIdx.x;  // over ELEM/4
    if (i < ELEM / 4) {
        float4 y = reinterpret_cast<const float4*>(g_y2)[i];
        float4 xv = reinterpret_cast<const float4*>(x)[i];
        int c = (i * 4) & 63;
        float4 r;
        r.x = fmaxf(y.x * g_s2[c + 0] + g_t2[c + 0] + xv.x, 0.f);
        r.y = fmaxf(y.y * g_s2[c + 1] + g_t2[c + 1] + xv.y, 0.f);
        r.z = fmaxf(y.z * g_s2[c + 2] + g_t2[c + 2] + xv.z, 0.f);
        r.w = fmaxf(y.w * g_s2[c + 3] + g_t2[c + 3] + xv.w, 0.f);
        reinterpret_cast<float4*>(out)[i] = r;
    }
}

// ---------------- launch -----------------------------------------------------
extern "C" void kernel_launch(void* const* d_in, const int* in_sizes, int n_in,
                              void* d_out, int out_size) {
    const float* x       = (const float*)d_in[0];
    const int*   ei      = (const int*)d_in[1];   // int32 (JAX x64 disabled)
    const float* W       = (const float*)d_in[2];
    // d_in[3] = b       : cancels through BN1 mean (no-op)
    const float* g1      = (const float*)d_in[4];
    const float* b1      = (const float*)d_in[5];
    const float* cw      = (const float*)d_in[6];
    // d_in[7] = conv_b  : cancels through BN2 mean (no-op)
    const float* g2      = (const float*)d_in[8];
    const float* b2      = (const float*)d_in[9];
    float* out = (float*)d_out;

    k_init<<<4, 256>>>();
    k_deg<<<(EE + 255) / 256, 256>>>(ei);
    k_scan<<<1, 1024>>>();
    k_fill<<<(EE + 255) / 256, 256>>>(ei);
    k_wt<<<(CC * CC * 9 + 255) / 256, 256>>>(cw);
    k_xw<<<BTN / 64, 64>>>(x, W);
    k_agg<<<(BTN * 32 + 255) / 256, 256>>>();
    k_stats<<<512, 256>>>(0);
    k_fin<<<1, 64>>>(g1, b1, 0);
    k_conv<<<BT * 16, 64>>>();
    k_stats<<<512, 256>>>(1);
    k_fin<<<1, 64>>>(g2, b2, 1);
    k_final<<<(ELEM / 4 + 255) / 256, 256>>>(x, out);
}

// round 6
// speedup vs baseline: 1.9788x; 1.9788x over previous
#include <cuda_runtime.h>
#include <cuda_bf16.h>
#include <cstdint>

// Problem constants
#define BB   4
#define TT   32
#define NN   1000
#define CC   64
#define EE   16000
#define BT   (BB*TT)           // 128
#define BTN  (BT*NN)           // 128000
#define ELEM (BTN*CC)          // 8192000
#define EPSV 1e-5f

// ---------------- device scratch ---------------------------------------------
__device__ __align__(16) float g_xw[ELEM];   // x @ W
__device__ __align__(16) float g_so[ELEM];   // GCN aggregate (pre-BN1)
__device__ __align__(16) float g_y2[ELEM];   // conv output (pre-BN2)
__device__ __align__(16) __nv_bfloat16 g_ah[ELEM];  // relu(bn1(so)) hi split
__device__ __align__(16) __nv_bfloat16 g_al[ELEM];  // lo split
__device__ __align__(16) __nv_bfloat16 g_wh[9 * CC * CC];  // [tap][c][ci] hi
__device__ __align__(16) __nv_bfloat16 g_wl[9 * CC * CC];  // lo
__device__ int   g_cnt[NN];
__device__ int   g_cur[NN];
__device__ int   g_off[NN + 1];
__device__ float g_dinv[NN];
__device__ int   g_src[EE];
__device__ float g_nrm[EE];
__device__ float g_stats[4 * CC];            // sum1, sq1, sum2, sq2
__device__ float g_s1[CC], g_t1[CC], g_s2[CC], g_t2[CC];

// ---------------- warp-MMA helpers (sm_80+ path; sm_100 target OK) ----------
__device__ __forceinline__ void ldsm4(uint32_t* r, const void* p) {
    uint32_t a = (uint32_t)__cvta_generic_to_shared(p);
    asm volatile("ldmatrix.sync.aligned.m8n8.x4.shared.b16 {%0,%1,%2,%3}, [%4];"
                 : "=r"(r[0]), "=r"(r[1]), "=r"(r[2]), "=r"(r[3]) : "r"(a));
}
__device__ __forceinline__ void ldsm2(uint32_t* r, const void* p) {
    uint32_t a = (uint32_t)__cvta_generic_to_shared(p);
    asm volatile("ldmatrix.sync.aligned.m8n8.x2.shared.b16 {%0,%1}, [%2];"
                 : "=r"(r[0]), "=r"(r[1]) : "r"(a));
}
__device__ __forceinline__ void mma_bf16(float* d, const uint32_t* a,
                                         const uint32_t* b) {
    asm volatile(
        "mma.sync.aligned.m16n8k16.row.col.f32.bf16.bf16.f32 "
        "{%0,%1,%2,%3}, {%4,%5,%6,%7}, {%8,%9}, {%0,%1,%2,%3};"
        : "+f"(d[0]), "+f"(d[1]), "+f"(d[2]), "+f"(d[3])
        : "r"(a[0]), "r"(a[1]), "r"(a[2]), "r"(a[3]), "r"(b[0]), "r"(b[1]));
}

// ---------------- init -------------------------------------------------------
__global__ void k_init() {
    int i = blockIdx.x * blockDim.x + threadIdx.x;
    if (i < NN) { g_cnt[i] = 0; g_cur[i] = 0; }
    if (i < 4 * CC) g_stats[i] = 0.f;
}

// ---------------- degree histogram (edge_index is int32) --------------------
__global__ void k_deg(const int* __restrict__ ei) {
    int e = blockIdx.x * blockDim.x + threadIdx.x;
    if (e < EE) atomicAdd(&g_cnt[ei[EE + e]], 1);
}

// ---------------- scan: CSR offsets + dinv (single block) -------------------
__global__ void k_scan() {
    __shared__ int s[1024];
    int tid = threadIdx.x;
    int v = (tid < NN) ? g_cnt[tid] : 0;
    s[tid] = v;
    for (int d = 1; d < 1024; d <<= 1) {
        __syncthreads();
        int t = (tid >= d) ? s[tid - d] : 0;
        __syncthreads();
        s[tid] += t;
    }
    __syncthreads();
    if (tid < NN) {
        g_off[tid] = s[tid] - v;
        g_dinv[tid] = rsqrtf((float)(v + 1));
    }
    if (tid == NN - 1) g_off[NN] = s[tid];
}

// ---------------- CSR fill ---------------------------------------------------
__global__ void k_fill(const int* __restrict__ ei) {
    int e = blockIdx.x * blockDim.x + threadIdx.x;
    if (e < EE) {
        int sr = ei[e], ds = ei[EE + e];
        int pos = atomicAdd(&g_cur[ds], 1);
        int idx = g_off[ds] + pos;
        g_src[idx] = sr;
        g_nrm[idx] = g_dinv[sr] * g_dinv[ds];
    }
}

// ---------------- conv weight split prep: [tap][c][ci] hi/lo bf16 -----------
__global__ void k_wprep(const float* __restrict__ cw) {
    int i = blockIdx.x * blockDim.x + threadIdx.x;  // over 9*64*64
    if (i < 9 * CC * CC) {
        int tap = i >> 12;
        int c   = (i >> 6) & 63;
        int ci  = i & 63;
        float w = cw[(c * CC + ci) * 9 + tap];
        __nv_bfloat16 h = __float2bfloat16(w);
        g_wh[i] = h;
        g_wl[i] = __float2bfloat16(w - __bfloat162float(h));
    }
}

// ---------------- xw = x @ W  (tile 64x64, 64 threads, 8x8 microtile) -------
__global__ void __launch_bounds__(64) k_xw(const float* __restrict__ x,
                                           const float* __restrict__ W) {
    __shared__ float Xs[CC * 65];
    __shared__ float Ws[CC * CC];
    int tid = threadIdx.x;
    int r0 = blockIdx.x * 64;
    int ci = tid & 63;

    for (int i = tid; i < CC * CC; i += 64) Ws[i] = W[i];
    for (int i = tid; i < 64 * CC; i += 64) {
        int row = i >> 6;
        Xs[ci * 65 + row] = x[(r0 + row) * CC + ci];
    }
    __syncthreads();

    int tr = tid >> 3, tc = tid & 7;
    float acc[8][8];
#pragma unroll
    for (int i = 0; i < 8; i++)
#pragma unroll
        for (int j = 0; j < 8; j++) acc[i][j] = 0.f;

#pragma unroll 4
    for (int kk = 0; kk < CC; kk++) {
        float a[8], bw[8];
#pragma unroll
        for (int i = 0; i < 8; i++) a[i] = Xs[kk * 65 + tr * 8 + i];
#pragma unroll
        for (int j = 0; j < 8; j++) bw[j] = Ws[kk * CC + tc * 8 + j];
#pragma unroll
        for (int i = 0; i < 8; i++)
#pragma unroll
            for (int j = 0; j < 8; j++) acc[i][j] += a[i] * bw[j];
    }
#pragma unroll
    for (int i = 0; i < 8; i++) {
        int row = r0 + tr * 8 + i;
#pragma unroll
        for (int j = 0; j < 8; j++) g_xw[row * CC + tc * 8 + j] = acc[i][j];
    }
}

// ---------------- GCN aggregation: warp per (bt, n) -------------------------
__global__ void k_agg() {
    int warp = (blockIdx.x * blockDim.x + threadIdx.x) >> 5;
    int lane = threadIdx.x & 31;
    if (warp >= BTN) return;
    int bt = warp / NN;
    int n  = warp - bt * NN;
    int base_bt = bt * NN * CC;

    float dv = g_dinv[n];
    float self_w = dv * dv;
    float2 v = *(const float2*)&g_xw[base_bt + n * CC + lane * 2];
    float2 acc = make_float2(self_w * v.x, self_w * v.y);

    int e0 = g_off[n], e1 = g_off[n + 1];
    for (int e = e0; e < e1; e++) {
        int sr = g_src[e];
        float w = g_nrm[e];
        float2 u = *(const float2*)&g_xw[base_bt + sr * CC + lane * 2];
        acc.x += w * u.x;
        acc.y += w * u.y;
    }
    *(float2*)&g_so[warp * CC + lane * 2] = acc;
}

// ---------------- per-channel stats (sum, sumsq) ----------------------------
__global__ void k_stats(int sel) {
    const float* __restrict__ src = sel ? g_y2 : g_so;
    int base = sel * 2 * CC;
    int c = threadIdx.x & 63;
    int q = threadIdx.x >> 6;
    float s = 0.f, s2 = 0.f;
    for (int r = blockIdx.x * 4 + q; r < BTN; r += gridDim.x * 4) {
        float v = src[r * CC + c];
        s += v;
        s2 += v * v;
    }
    __shared__ float sh[2][4][CC];
    sh[0][q][c] = s;
    sh[1][q][c] = s2;
    __syncthreads();
    if (q == 0) {
        s  = sh[0][0][c] + sh[0][1][c] + sh[0][2][c] + sh[0][3][c];
        s2 = sh[1][0][c] + sh[1][1][c] + sh[1][2][c] + sh[1][3][c];
        atomicAdd(&g_stats[base + c], s);
        atomicAdd(&g_stats[base + CC + c], s2);
    }
}

// ---------------- BN finalize ------------------------------------------------
__global__ void k_fin(const float* __restrict__ gamma,
                      const float* __restrict__ beta, int sel) {
    int c = threadIdx.x;
    int base = sel * 2 * CC;
    float inv_n = 1.f / (float)BTN;
    float mean = g_stats[base + c] * inv_n;
    float var  = g_stats[base + CC + c] * inv_n - mean * mean;
    float rstd = rsqrtf(var + EPSV);
    float s = gamma[c] * rstd;
    float t = beta[c] - mean * s;
    if (sel) { g_s2[c] = s; g_t2[c] = t; }
    else     { g_s1[c] = s; g_t1[c] = t; }
}

// ---------------- convert: relu(bn1(so)) -> bf16 hi/lo split ----------------
__global__ void k_cvt() {
    int i = blockIdx.x * blockDim.x + threadIdx.x;
    if (i < ELEM / 4) {
        float4 v = reinterpret_cast<const float4*>(g_so)[i];
        int c = (i * 4) & 63;
        float r0 = fmaxf(v.x * g_s1[c + 0] + g_t1[c + 0], 0.f);
        float r1 = fmaxf(v.y * g_s1[c + 1] + g_t1[c + 1], 0.f);
        float r2 = fmaxf(v.z * g_s1[c + 2] + g_t1[c + 2], 0.f);
        float r3 = fmaxf(v.w * g_s1[c + 3] + g_t1[c + 3], 0.f);
        __nv_bfloat16 h0 = __float2bfloat16(r0);
        __nv_bfloat16 h1 = __float2bfloat16(r1);
        __nv_bfloat16 h2 = __float2bfloat16(r2);
        __nv_bfloat16 h3 = __float2bfloat16(r3);
        __nv_bfloat162 hh;
        hh.x = h0; hh.y = h1;
        reinterpret_cast<__nv_bfloat162*>(g_ah)[i * 2] = hh;
        hh.x = h2; hh.y = h3;
        reinterpret_cast<__nv_bfloat162*>(g_ah)[i * 2 + 1] = hh;
        __nv_bfloat162 ll;
        ll.x = __float2bfloat16(r0 - __bfloat162float(h0));
        ll.y = __float2bfloat16(r1 - __bfloat162float(h1));
        reinterpret_cast<__nv_bfloat162*>(g_al)[i * 2] = ll;
        ll.x = __float2bfloat16(r2 - __bfloat162float(h2));
        ll.y = __float2bfloat16(r3 - __bfloat162float(h3));
        reinterpret_cast<__nv_bfloat162*>(g_al)[i * 2 + 1] = ll;
    }
}

// ---------------- temporal conv via warp-level bf16 split MMA ---------------
// Block tile: [M=128 nodes] x [N=64 channels] for one (bt, ntile).
// 8 warps in 4x2 grid; warp tile 32x32 = 2 m16 x 4 n8 fragments.
// K=64 per tap, 9 taps accumulated in registers; 3 chains (al*wl dropped).
// Smem rows padded to 72 bf16 (144 B): 16B-aligned rows, conflict-free ldmatrix.
#define APITCH 72
#define A_SPLIT_BYTES (128 * APITCH * 2)          // 18432
#define W_BASE        (2 * A_SPLIT_BYTES)         // 36864
#define W_SPLIT_BYTES (64 * APITCH * 2)           // 9216
#define CONV_SMEM     (W_BASE + 2 * W_SPLIT_BYTES) // 55296

__global__ void __launch_bounds__(256) k_conv_mma() {
    extern __shared__ char smem[];
    int tid = threadIdx.x;
    int wid = tid >> 5;
    int lane = tid & 31;
    int tile = blockIdx.x;              // 0..1023
    int bt = tile >> 3;
    int n0 = (tile & 7) << 7;
    int t = bt & 31;
    int wm = wid >> 1;                  // 0..3 : m-32 block
    int wn = wid & 1;                   // 0..1 : n-32 block

    float acc[8][4];
#pragma unroll
    for (int f = 0; f < 8; f++)
#pragma unroll
        for (int j = 0; j < 4; j++) acc[f][j] = 0.f;

    for (int k = 0; k < 9; k++) {
        int tp = t + k - 4;
        if (tp < 0 || tp >= TT) continue;      // block-uniform
        int btp = (bt & ~31) + tp;

        __syncthreads();   // prior ldmatrix reads done before overwrite

        // A tile: 128 rows x 64 bf16, hi+lo  (2048 uint4)
#pragma unroll
        for (int it = 0; it < 8; it++) {
            int id = tid + (it << 8);
            int split = id >> 10;
            int rem = id & 1023;
            int row = rem >> 3;
            int q = rem & 7;
            int n = n0 + row;
            uint4 v = make_uint4(0, 0, 0, 0);
            if (n < NN) {
                const uint4* src = reinterpret_cast<const uint4*>(
                    (split ? g_al : g_ah) + (((size_t)btp * NN + n) << 6));
                v = src[q];
            }
            *reinterpret_cast<uint4*>(
                smem + split * A_SPLIT_BYTES + row * 144 + q * 16) = v;
        }
        // W tile for tap k: 64 rows x 64, hi+lo  (1024 uint4)
#pragma unroll
        for (int it = 0; it < 4; it++) {
            int id = tid + (it << 8);
            int split = id >> 9;
            int rem = id & 511;
            int row = rem >> 3;
            int q = rem & 7;
            const uint4* src = reinterpret_cast<const uint4*>(
                (split ? g_wl : g_wh) + ((k * CC + row) << 6));
            uint4 v = src[q];
            *reinterpret_cast<uint4*>(
                smem + W_BASE + split * W_SPLIT_BYTES + row * 144 + q * 16) = v;
        }
        __syncthreads();

#pragma unroll
        for (int ks = 0; ks < 4; ks++) {
            int k0 = ks << 4;
            uint32_t ah[2][4], al[2][4];
            int ar = (lane & 15);
            int ac = k0 + ((lane >> 4) << 3);
#pragma unroll
            for (int mt = 0; mt < 2; mt++) {
                int row = wm * 32 + mt * 16 + ar;
                ldsm4(ah[mt], smem + row * 144 + ac * 2);
                ldsm4(al[mt], smem + A_SPLIT_BYTES + row * 144 + ac * 2);
            }
            uint32_t bh[4][2], bl[4][2];
            int br = (lane & 7);
            int bc = k0 + (((lane >> 3) & 1) << 3);
#pragma unroll
            for (int nt = 0; nt < 4; nt++) {
                int row = wn * 32 + nt * 8 + br;
                ldsm2(bh[nt], smem + W_BASE + row * 144 + bc * 2);
                ldsm2(bl[nt], smem + W_BASE + W_SPLIT_BYTES + row * 144 + bc * 2);
            }
#pragma unroll
            for (int mt = 0; mt < 2; mt++)
#pragma unroll
                for (int nt = 0; nt < 4; nt++) {
                    float* d = acc[mt * 4 + nt];
                    mma_bf16(d, ah[mt], bh[nt]);
                    mma_bf16(d, al[mt], bh[nt]);
                    mma_bf16(d, ah[mt], bl[nt]);
                }
        }
    }

    // epilogue: write fragments to g_y2 [btn][64]
#pragma unroll
    for (int mt = 0; mt < 2; mt++) {
#pragma unroll
        for (int nt = 0; nt < 4; nt++) {
            float* d = acc[mt * 4 + nt];
            int r0 = n0 + wm * 32 + mt * 16 + (lane >> 2);
            int col = wn * 32 + nt * 8 + ((lane & 3) << 1);
            if (r0 < NN) {
                float2 v0 = make_float2(d[0], d[1]);
                *reinterpret_cast<float2*>(
                    g_y2 + (((size_t)bt * NN + r0) << 6) + col) = v0;
            }
            int r1 = r0 + 8;
            if (r1 < NN) {
                float2 v1 = make_float2(d[2], d[3]);
                *reinterpret_cast<float2*>(
                    g_y2 + (((size_t)bt * NN + r1) << 6) + col) = v1;
            }
        }
    }
}

// ---------------- final: relu(bn2(y2) + x) ----------------------------------
__global__ void k_final(const float* __restrict__ x, float* __restrict__ out) {
    int i = blockIdx.x * blockDim.x + threadIdx.x;
    if (i < ELEM / 4) {
        float4 y = reinterpret_cast<const float4*>(g_y2)[i];
        float4 xv = reinterpret_cast<const float4*>(x)[i];
        int c = (i * 4) & 63;
        float4 r;
        r.x = fmaxf(y.x * g_s2[c + 0] + g_t2[c + 0] + xv.x, 0.f);
        r.y = fmaxf(y.y * g_s2[c + 1] + g_t2[c + 1] + xv.y, 0.f);
        r.z = fmaxf(y.z * g_s2[c + 2] + g_t2[c + 2] + xv.z, 0.f);
        r.w = fmaxf(y.w * g_s2[c + 3] + g_t2[c + 3] + xv.w, 0.f);
        reinterpret_cast<float4*>(out)[i] = r;
    }
}

// ---------------- launch -----------------------------------------------------
extern "C" void kernel_launch(void* const* d_in, const int* in_sizes, int n_in,
                              void* d_out, int out_size) {
    const float* x  = (const float*)d_in[0];
    const int*   ei = (const int*)d_in[1];   // int32 (JAX x64 disabled)
    const float* W  = (const float*)d_in[2];
    const float* g1 = (const float*)d_in[4];
    const float* b1 = (const float*)d_in[5];
    const float* cw = (const float*)d_in[6];
    const float* g2 = (const float*)d_in[8];
    const float* b2 = (const float*)d_in[9];
    float* out = (float*)d_out;

    cudaFuncSetAttribute(k_conv_mma,
                         cudaFuncAttributeMaxDynamicSharedMemorySize,
                         CONV_SMEM);

    k_init<<<4, 256>>>();
    k_deg<<<(EE + 255) / 256, 256>>>(ei);
    k_scan<<<1, 1024>>>();
    k_fill<<<(EE + 255) / 256, 256>>>(ei);
    k_wprep<<<(9 * CC * CC + 255) / 256, 256>>>(cw);
    k_xw<<<BTN / 64, 64>>>(x, W);
    k_agg<<<(BTN * 32 + 255) / 256, 256>>>();
    k_stats<<<512, 256>>>(0);
    k_fin<<<1, 64>>>(g1, b1, 0);
    k_cvt<<<(ELEM / 4 + 255) / 256, 256>>>();
    k_conv_mma<<<BT * 8, 256, CONV_SMEM>>>();
    k_stats<<<512, 256>>>(1);
    k_fin<<<1, 64>>>(g2, b2, 1);
    k_final<<<(ELEM / 4 + 255) / 256, 256>>>(x, out);
}

// round 7
// speedup vs baseline: 2.4305x; 1.2283x over previous
#include <cuda_runtime.h>
#include <cuda_bf16.h>
#include <cstdint>

// Problem constants
#define BB   4
#define TT   32
#define NN   1000
#define CC   64
#define EE   16000
#define BT   (BB*TT)           // 128
#define BTN  (BT*NN)           // 128000
#define ELEM (BTN*CC)          // 8192000
#define EPSV 1e-5f

// ---------------- device scratch ---------------------------------------------
__device__ __align__(16) float g_xw[ELEM];   // x @ W
__device__ __align__(16) float g_so[ELEM];   // GCN aggregate (pre-BN1)
__device__ __align__(16) float g_y2[ELEM];   // conv output (pre-BN2)
__device__ __align__(16) __nv_bfloat16 g_ah[ELEM];  // relu(bn1(so)) hi split
__device__ __align__(16) __nv_bfloat16 g_al[ELEM];  // lo split
__device__ __align__(16) __nv_bfloat16 g_wh[9 * CC * CC];  // conv [tap][c][ci] hi
__device__ __align__(16) __nv_bfloat16 g_wl[9 * CC * CC];  // lo
__device__ __align__(16) __nv_bfloat16 g_gwh[CC * CC];     // gcn W^T [d][ci] hi
__device__ __align__(16) __nv_bfloat16 g_gwl[CC * CC];     // lo
__device__ int   g_cnt[NN];
__device__ int   g_cur[NN];
__device__ int   g_off[NN + 1];
__device__ float g_dinv[NN];
__device__ int   g_src[EE];
__device__ float g_nrm[EE];
__device__ float g_stats[4 * CC];            // [0:64)=s1 [64:128)=q1 [128:192)=s2 [192:256)=q2
__device__ float g_s1[CC], g_t1[CC], g_s2[CC], g_t2[CC];

// ---------------- warp-MMA helpers -------------------------------------------
__device__ __forceinline__ void ldsm4(uint32_t* r, const void* p) {
    uint32_t a = (uint32_t)__cvta_generic_to_shared(p);
    asm volatile("ldmatrix.sync.aligned.m8n8.x4.shared.b16 {%0,%1,%2,%3}, [%4];"
                 : "=r"(r[0]), "=r"(r[1]), "=r"(r[2]), "=r"(r[3]) : "r"(a));
}
__device__ __forceinline__ void ldsm2(uint32_t* r, const void* p) {
    uint32_t a = (uint32_t)__cvta_generic_to_shared(p);
    asm volatile("ldmatrix.sync.aligned.m8n8.x2.shared.b16 {%0,%1}, [%2];"
                 : "=r"(r[0]), "=r"(r[1]) : "r"(a));
}
__device__ __forceinline__ void mma_bf16(float* d, const uint32_t* a,
                                         const uint32_t* b) {
    asm volatile(
        "mma.sync.aligned.m16n8k16.row.col.f32.bf16.bf16.f32 "
        "{%0,%1,%2,%3}, {%4,%5,%6,%7}, {%8,%9}, {%0,%1,%2,%3};"
        : "+f"(d[0]), "+f"(d[1]), "+f"(d[2]), "+f"(d[3])
        : "r"(a[0]), "r"(a[1]), "r"(a[2]), "r"(a[3]), "r"(b[0]), "r"(b[1]));
}
__device__ __forceinline__ uint32_t pk(__nv_bfloat16 a, __nv_bfloat16 b) {
    __nv_bfloat162 t; t.x = a; t.y = b;
    return *reinterpret_cast<uint32_t*>(&t);
}

// Shared tile geometry (rows padded to 144 B: 16B-aligned, conflict-free ldmatrix)
#define A_SPLIT_BYTES (128 * 144)                  // 18432
#define W_BASE        (2 * A_SPLIT_BYTES)          // 36864
#define W_SPLIT_BYTES (64 * 144)                   // 9216
#define TILE_SMEM     (W_BASE + 2 * W_SPLIT_BYTES) // 55296

// ---------------- init -------------------------------------------------------
__global__ void k_init() {
    int i = blockIdx.x * blockDim.x + threadIdx.x;
    if (i < NN) { g_cnt[i] = 0; g_cur[i] = 0; }
    if (i < 4 * CC) g_stats[i] = 0.f;
}

// ---------------- degree histogram (edge_index is int32) --------------------
__global__ void k_deg(const int* __restrict__ ei) {
    int e = blockIdx.x * blockDim.x + threadIdx.x;
    if (e < EE) atomicAdd(&g_cnt[ei[EE + e]], 1);
}

// ---------------- scan: CSR offsets + dinv (single block) -------------------
__global__ void k_scan() {
    __shared__ int s[1024];
    int tid = threadIdx.x;
    int v = (tid < NN) ? g_cnt[tid] : 0;
    s[tid] = v;
    for (int d = 1; d < 1024; d <<= 1) {
        __syncthreads();
        int t = (tid >= d) ? s[tid - d] : 0;
        __syncthreads();
        s[tid] += t;
    }
    __syncthreads();
    if (tid < NN) {
        g_off[tid] = s[tid] - v;
        g_dinv[tid] = rsqrtf((float)(v + 1));
    }
    if (tid == NN - 1) g_off[NN] = s[tid];
}

// ---------------- CSR fill ---------------------------------------------------
__global__ void k_fill(const int* __restrict__ ei) {
    int e = blockIdx.x * blockDim.x + threadIdx.x;
    if (e < EE) {
        int sr = ei[e], ds = ei[EE + e];
        int pos = atomicAdd(&g_cur[ds], 1);
        int idx = g_off[ds] + pos;
        g_src[idx] = sr;
        g_nrm[idx] = g_dinv[sr] * g_dinv[ds];
    }
}

// ---------------- weight split prep (conv taps + gcn W^T) -------------------
__global__ void k_wprep(const float* __restrict__ cw, const float* __restrict__ W) {
    int i = blockIdx.x * blockDim.x + threadIdx.x;
    if (i < 9 * CC * CC) {
        int tap = i >> 12;
        int c   = (i >> 6) & 63;
        int ci  = i & 63;
        float w = cw[(c * CC + ci) * 9 + tap];
        __nv_bfloat16 h = __float2bfloat16(w);
        g_wh[i] = h;
        g_wl[i] = __float2bfloat16(w - __bfloat162float(h));
    }
    if (i < CC * CC) {
        int d  = i >> 6;
        int ci = i & 63;
        float w = W[ci * CC + d];     // transpose: [d][ci]
        __nv_bfloat16 h = __float2bfloat16(w);
        g_gwh[i] = h;
        g_gwl[i] = __float2bfloat16(w - __bfloat162float(h));
    }
}

// ---------------- xw = x @ W via MMA (in-kernel split conversion) -----------
// Block: 128 rows x 64 cols, K=64; 8 warps 4x2; 3 chains.
__global__ void __launch_bounds__(256) k_xw_mma(const float* __restrict__ x) {
    extern __shared__ char smem[];
    int tid = threadIdx.x;
    int wid = tid >> 5;
    int lane = tid & 31;
    int r0 = blockIdx.x << 7;           // 1000 blocks
    int wm = wid >> 1, wn = wid & 1;

    // load + convert X tile: 2048 float4
#pragma unroll
    for (int it = 0; it < 8; it++) {
        int id = tid + (it << 8);
        int row = id >> 4;
        int q = id & 15;                 // float4 within row
        float4 v = *reinterpret_cast<const float4*>(
            x + ((size_t)(r0 + row) << 6) + (q << 2));
        __nv_bfloat16 h0 = __float2bfloat16(v.x);
        __nv_bfloat16 h1 = __float2bfloat16(v.y);
        __nv_bfloat16 h2 = __float2bfloat16(v.z);
        __nv_bfloat16 h3 = __float2bfloat16(v.w);
        uint2 hh = make_uint2(pk(h0, h1), pk(h2, h3));
        uint2 ll = make_uint2(
            pk(__float2bfloat16(v.x - __bfloat162float(h0)),
               __float2bfloat16(v.y - __bfloat162float(h1))),
            pk(__float2bfloat16(v.z - __bfloat162float(h2)),
               __float2bfloat16(v.w - __bfloat162float(h3))));
        *reinterpret_cast<uint2*>(smem + row * 144 + q * 8) = hh;
        *reinterpret_cast<uint2*>(smem + A_SPLIT_BYTES + row * 144 + q * 8) = ll;
    }
    // W^T tiles hi/lo
#pragma unroll
    for (int it = 0; it < 4; it++) {
        int id = tid + (it << 8);
        int split = id >> 9;
        int rem = id & 511;
        int row = rem >> 3;
        int q = rem & 7;
        uint4 v = reinterpret_cast<const uint4*>(
            (split ? g_gwl : g_gwh) + (row << 6))[q];
        *reinterpret_cast<uint4*>(
            smem + W_BASE + split * W_SPLIT_BYTES + row * 144 + q * 16) = v;
    }
    __syncthreads();

    float acc[8][4];
#pragma unroll
    for (int f = 0; f < 8; f++)
#pragma unroll
        for (int j = 0; j < 4; j++) acc[f][j] = 0.f;

#pragma unroll
    for (int ks = 0; ks < 4; ks++) {
        int k0 = ks << 4;
        uint32_t ah[2][4], al[2][4];
        int ar = (lane & 15);
        int ac = k0 + ((lane >> 4) << 3);
#pragma unroll
        for (int mt = 0; mt < 2; mt++) {
            int row = wm * 32 + mt * 16 + ar;
            ldsm4(ah[mt], smem + row * 144 + ac * 2);
            ldsm4(al[mt], smem + A_SPLIT_BYTES + row * 144 + ac * 2);
        }
        uint32_t bh[4][2], bl[4][2];
        int br = (lane & 7);
        int bc = k0 + (((lane >> 3) & 1) << 3);
#pragma unroll
        for (int nt = 0; nt < 4; nt++) {
            int row = wn * 32 + nt * 8 + br;
            ldsm2(bh[nt], smem + W_BASE + row * 144 + bc * 2);
            ldsm2(bl[nt], smem + W_BASE + W_SPLIT_BYTES + row * 144 + bc * 2);
        }
#pragma unroll
        for (int mt = 0; mt < 2; mt++)
#pragma unroll
            for (int nt = 0; nt < 4; nt++) {
                float* d = acc[mt * 4 + nt];
                mma_bf16(d, ah[mt], bh[nt]);
                mma_bf16(d, al[mt], bh[nt]);
                mma_bf16(d, ah[mt], bl[nt]);
            }
    }
#pragma unroll
    for (int mt = 0; mt < 2; mt++)
#pragma unroll
        for (int nt = 0; nt < 4; nt++) {
            float* d = acc[mt * 4 + nt];
            int row = r0 + wm * 32 + mt * 16 + (lane >> 2);
            int col = wn * 32 + nt * 8 + ((lane & 3) << 1);
            *reinterpret_cast<float2*>(g_xw + ((size_t)row << 6) + col) =
                make_float2(d[0], d[1]);
            *reinterpret_cast<float2*>(g_xw + ((size_t)(row + 8) << 6) + col) =
                make_float2(d[2], d[3]);
        }
}

// ---------------- GCN aggregation + fused BN1 stats -------------------------
// 64 rows per block (8 per warp); stats reduced in smem, one atomic round/block.
__global__ void __launch_bounds__(256) k_agg() {
    __shared__ float ss[8][CC], sq[8][CC];
    int tid = threadIdx.x;
    int wid = tid >> 5;
    int lane = tid & 31;
    float s0 = 0.f, s1v = 0.f, q0 = 0.f, q1 = 0.f;
    int base = (blockIdx.x << 6) + (wid << 3);

    for (int i = 0; i < 8; i++) {
        int idx = base + i;              // bt*NN + n
        int bt = idx / NN;
        int n  = idx - bt * NN;
        int base_bt = bt * NN * CC;

        float dv = g_dinv[n];
        float self_w = dv * dv;
        float2 v = *(const float2*)&g_xw[base_bt + n * CC + lane * 2];
        float2 acc = make_float2(self_w * v.x, self_w * v.y);

        int e0 = g_off[n], e1 = g_off[n + 1];
        for (int e = e0; e < e1; e++) {
            int sr = g_src[e];
            float w = g_nrm[e];
            float2 u = *(const float2*)&g_xw[base_bt + sr * CC + lane * 2];
            acc.x += w * u.x;
            acc.y += w * u.y;
        }
        *(float2*)&g_so[idx * CC + lane * 2] = acc;
        s0 += acc.x; q0 += acc.x * acc.x;
        s1v += acc.y; q1 += acc.y * acc.y;
    }
    ss[wid][lane * 2] = s0;  ss[wid][lane * 2 + 1] = s1v;
    sq[wid][lane * 2] = q0;  sq[wid][lane * 2 + 1] = q1;
    __syncthreads();
    if (tid < CC) {
        float s = 0.f;
#pragma unroll
        for (int w = 0; w < 8; w++) s += ss[w][tid];
        atomicAdd(&g_stats[tid], s);
    } else if (tid < 2 * CC) {
        int c = tid - CC;
        float s = 0.f;
#pragma unroll
        for (int w = 0; w < 8; w++) s += sq[w][c];
        atomicAdd(&g_stats[CC + c], s);
    }
}

// ---------------- BN finalize ------------------------------------------------
__global__ void k_fin(const float* __restrict__ gamma,
                      const float* __restrict__ beta, int sel) {
    int c = threadIdx.x;
    int base = sel * 2 * CC;
    float inv_n = 1.f / (float)BTN;
    float mean = g_stats[base + c] * inv_n;
    float var  = g_stats[base + CC + c] * inv_n - mean * mean;
    float rstd = rsqrtf(var + EPSV);
    float s = gamma[c] * rstd;
    float t = beta[c] - mean * s;
    if (sel) { g_s2[c] = s; g_t2[c] = t; }
    else     { g_s1[c] = s; g_t1[c] = t; }
}

// ---------------- convert: relu(bn1(so)) -> bf16 hi/lo split ----------------
__global__ void k_cvt() {
    int i = blockIdx.x * blockDim.x + threadIdx.x;
    if (i < ELEM / 4) {
        float4 v = reinterpret_cast<const float4*>(g_so)[i];
        int c = (i * 4) & 63;
        float r0 = fmaxf(v.x * g_s1[c + 0] + g_t1[c + 0], 0.f);
        float r1 = fmaxf(v.y * g_s1[c + 1] + g_t1[c + 1], 0.f);
        float r2 = fmaxf(v.z * g_s1[c + 2] + g_t1[c + 2], 0.f);
        float r3 = fmaxf(v.w * g_s1[c + 3] + g_t1[c + 3], 0.f);
        __nv_bfloat16 h0 = __float2bfloat16(r0);
        __nv_bfloat16 h1 = __float2bfloat16(r1);
        __nv_bfloat16 h2 = __float2bfloat16(r2);
        __nv_bfloat16 h3 = __float2bfloat16(r3);
        uint2 hh = make_uint2(pk(h0, h1), pk(h2, h3));
        reinterpret_cast<uint2*>(g_ah)[i] = hh;
        uint2 ll = make_uint2(
            pk(__float2bfloat16(r0 - __bfloat162float(h0)),
               __float2bfloat16(r1 - __bfloat162float(h1))),
            pk(__float2bfloat16(r2 - __bfloat162float(h2)),
               __float2bfloat16(r3 - __bfloat162float(h3))));
        reinterpret_cast<uint2*>(g_al)[i] = ll;
    }
}

// ---------------- temporal conv via warp MMA + fused BN2 stats --------------
__global__ void __launch_bounds__(256) k_conv_mma() {
    extern __shared__ char smem[];
    int tid = threadIdx.x;
    int wid = tid >> 5;
    int lane = tid & 31;
    int tile = blockIdx.x;
    int bt = tile >> 3;
    int n0 = (tile & 7) << 7;
    int t = bt & 31;
    int wm = wid >> 1, wn = wid & 1;

    float acc[8][4];
#pragma unroll
    for (int f = 0; f < 8; f++)
#pragma unroll
        for (int j = 0; j < 4; j++) acc[f][j] = 0.f;

    for (int k = 0; k < 9; k++) {
        int tp = t + k - 4;
        if (tp < 0 || tp >= TT) continue;
        int btp = (bt & ~31) + tp;

        __syncthreads();
#pragma unroll
        for (int it = 0; it < 8; it++) {
            int id = tid + (it << 8);
            int split = id >> 10;
            int rem = id & 1023;
            int row = rem >> 3;
            int q = rem & 7;
            int n = n0 + row;
            uint4 v = make_uint4(0, 0, 0, 0);
            if (n < NN) {
                const uint4* src = reinterpret_cast<const uint4*>(
                    (split ? g_al : g_ah) + (((size_t)btp * NN + n) << 6));
                v = src[q];
            }
            *reinterpret_cast<uint4*>(
                smem + split * A_SPLIT_BYTES + row * 144 + q * 16) = v;
        }
#pragma unroll
        for (int it = 0; it < 4; it++) {
            int id = tid + (it << 8);
            int split = id >> 9;
            int rem = id & 511;
            int row = rem >> 3;
            int q = rem & 7;
            uint4 v = reinterpret_cast<const uint4*>(
                (split ? g_wl : g_wh) + ((k * CC + row) << 6))[q];
            *reinterpret_cast<uint4*>(
                smem + W_BASE + split * W_SPLIT_BYTES + row * 144 + q * 16) = v;
        }
        __syncthreads();

#pragma unroll
        for (int ks = 0; ks < 4; ks++) {
            int k0 = ks << 4;
            uint32_t ah[2][4], al[2][4];
            int ar = (lane & 15);
            int ac = k0 + ((lane >> 4) << 3);
#pragma unroll
            for (int mt = 0; mt < 2; mt++) {
                int row = wm * 32 + mt * 16 + ar;
                ldsm4(ah[mt], smem + row * 144 + ac * 2);
                ldsm4(al[mt], smem + A_SPLIT_BYTES + row * 144 + ac * 2);
            }
            uint32_t bh[4][2], bl[4][2];
            int br = (lane & 7);
            int bc = k0 + (((lane >> 3) & 1) << 3);
#pragma unroll
            for (int nt = 0; nt < 4; nt++) {
                int row = wn * 32 + nt * 8 + br;
                ldsm2(bh[nt], smem + W_BASE + row * 144 + bc * 2);
                ldsm2(bl[nt], smem + W_BASE + W_SPLIT_BYTES + row * 144 + bc * 2);
            }
#pragma unroll
            for (int mt = 0; mt < 2; mt++)
#pragma unroll
                for (int nt = 0; nt < 4; nt++) {
                    float* d = acc[mt * 4 + nt];
                    mma_bf16(d, ah[mt], bh[nt]);
                    mma_bf16(d, al[mt], bh[nt]);
                    mma_bf16(d, ah[mt], bl[nt]);
                }
        }
    }

    // epilogue: write g_y2 + accumulate BN2 stats
    float cs[8], cq[8];
#pragma unroll
    for (int j = 0; j < 8; j++) { cs[j] = 0.f; cq[j] = 0.f; }

#pragma unroll
    for (int mt = 0; mt < 2; mt++) {
        int r0 = n0 + wm * 32 + mt * 16 + (lane >> 2);
        int r1 = r0 + 8;
        bool v0 = r0 < NN, v1 = r1 < NN;
#pragma unroll
        for (int nt = 0; nt < 4; nt++) {
            float* d = acc[mt * 4 + nt];
            int col = wn * 32 + nt * 8 + ((lane & 3) << 1);
            if (v0) {
                *reinterpret_cast<float2*>(
                    g_y2 + (((size_t)bt * NN + r0) << 6) + col) =
                    make_float2(d[0], d[1]);
                cs[nt * 2] += d[0];     cq[nt * 2] += d[0] * d[0];
                cs[nt * 2 + 1] += d[1]; cq[nt * 2 + 1] += d[1] * d[1];
            }
            if (v1) {
                *reinterpret_cast<float2*>(
                    g_y2 + (((size_t)bt * NN + r1) << 6) + col) =
                    make_float2(d[2], d[3]);
                cs[nt * 2] += d[2];     cq[nt * 2] += d[2] * d[2];
                cs[nt * 2 + 1] += d[3]; cq[nt * 2 + 1] += d[3] * d[3];
            }
        }
    }
#pragma unroll
    for (int off = 4; off < 32; off <<= 1) {
#pragma unroll
        for (int j = 0; j < 8; j++) {
            cs[j] += __shfl_xor_sync(0xffffffffu, cs[j], off);
            cq[j] += __shfl_xor_sync(0xffffffffu, cq[j], off);
        }
    }
    if ((lane >> 2) == 0) {
#pragma unroll
        for (int nt = 0; nt < 4; nt++)
#pragma unroll
            for (int h = 0; h < 2; h++) {
                int col = wn * 32 + nt * 8 + ((lane & 3) << 1) + h;
                atomicAdd(&g_stats[2 * CC + col], cs[nt * 2 + h]);
                atomicAdd(&g_stats[3 * CC + col], cq[nt * 2 + h]);
            }
    }
}

// ---------------- final: relu(bn2(y2) + x) ----------------------------------
__global__ void k_final(const float* __restrict__ x, float* __restrict__ out) {
    int i = blockIdx.x * blockDim.x + threadIdx.x;
    if (i < ELEM / 4) {
        float4 y = reinterpret_cast<const float4*>(g_y2)[i];
        float4 xv = reinterpret_cast<const float4*>(x)[i];
        int c = (i * 4) & 63;
        float4 r;
        r.x = fmaxf(y.x * g_s2[c + 0] + g_t2[c + 0] + xv.x, 0.f);
        r.y = fmaxf(y.y * g_s2[c + 1] + g_t2[c + 1] + xv.y, 0.f);
        r.z = fmaxf(y.z * g_s2[c + 2] + g_t2[c + 2] + xv.z, 0.f);
        r.w = fmaxf(y.w * g_s2[c + 3] + g_t2[c + 3] + xv.w, 0.f);
        reinterpret_cast<float4*>(out)[i] = r;
    }
}

// ---------------- launch -----------------------------------------------------
extern "C" void kernel_launch(void* const* d_in, const int* in_sizes, int n_in,
                              void* d_out, int out_size) {
    const float* x  = (const float*)d_in[0];
    const int*   ei = (const int*)d_in[1];   // int32 (JAX x64 disabled)
    const float* W  = (const float*)d_in[2];
    const float* g1 = (const float*)d_in[4];
    const float* b1 = (const float*)d_in[5];
    const float* cw = (const float*)d_in[6];
    const float* g2 = (const float*)d_in[8];
    const float* b2 = (const float*)d_in[9];
    float* out = (float*)d_out;

    cudaFuncSetAttribute(k_conv_mma,
                         cudaFuncAttributeMaxDynamicSharedMemorySize, TILE_SMEM);
    cudaFuncSetAttribute(k_xw_mma,
                         cudaFuncAttributeMaxDynamicSharedMemorySize, TILE_SMEM);

    k_init<<<4, 256>>>();
    k_deg<<<(EE + 255) / 256, 256>>>(ei);
    k_scan<<<1, 1024>>>();
    k_fill<<<(EE + 255) / 256, 256>>>(ei);
    k_wprep<<<(9 * CC * CC + 255) / 256, 256>>>(cw, W);
    k_xw_mma<<<BTN / 128, 256, TILE_SMEM>>>(x);
    k_agg<<<BTN / 64, 256>>>();
    k_fin<<<1, 64>>>(g1, b1, 0);
    k_cvt<<<(ELEM / 4 + 255) / 256, 256>>>();
    k_conv_mma<<<BT * 8, 256, TILE_SMEM>>>();
    k_fin<<<1, 64>>>(g2, b2, 1);
    k_final<<<(ELEM / 4 + 255) / 256, 256>>>(x, out);
}